// round 10
// baseline (speedup 1.0000x reference)
#include <cuda_runtime.h>
#include <cstdint>

#define NB 16
#define NL 1024
#define ND 768
#define NH 12
#define NDH 64
#define LD (NL*ND)          // 786432
#define NM (NB*NL)          // 16384

// ---------------- scratch (static device globals; no allocation) ----------
__device__ float g_xT[NB*LD];            // x transposed: [i][b], tf32 bits
__device__ float g_xq[NB*LD];            // gathered q input, tf32 bits
__device__ float g_xk[NB*LD];            // gathered k input, tf32 bits
__device__ float g_xv[NB*LD];            // x copy, tf32 bits
__device__ float g_q [NM*ND];            // (b,h,l,dh), tf32 bits, pre-scaled
__device__ float g_k [NM*ND];            // (b,h,l,dh), tf32 bits
__device__ float g_v [NM*ND];            // V^T: (b,h,dh,l), tf32 bits
__device__ float g_o [NM*ND];            // attention output, tf32 bits
__device__ float g_WT[4*ND*ND];          // transposed weights [n][k], tf32 bits

// 0.125 * log2(e)
#define SC_Q 0.18033688011112042f

// ---------------- helpers ---------------------------------------------------
__device__ __forceinline__ uint32_t f2tf32(float f) {
    uint32_t r;
    asm("cvt.rna.tf32.f32 %0, %1;" : "=r"(r) : "f"(f));
    return r;
}
__device__ __forceinline__ float tf32f(float f) {
    return __uint_as_float(f2tf32(f));
}
__device__ __forceinline__ float ex2(float x) {
    float r;
    asm("ex2.approx.f32 %0, %1;" : "=f"(r) : "f"(x));
    return r;
}
__device__ __forceinline__ uint32_t smem_u32(const void* p) {
    uint32_t a;
    asm("{ .reg .u64 t; cvta.to.shared.u64 t, %1; cvt.u32.u64 %0, t; }"
        : "=r"(a) : "l"(p));
    return a;
}
__device__ __forceinline__ void cp16(uint32_t saddr, const void* g) {
    asm volatile("cp.async.ca.shared.global [%0], [%1], 16;"
                 :: "r"(saddr), "l"(g));
}
#define CP_COMMIT() asm volatile("cp.async.commit_group;" ::: "memory")
#define CP_WAIT1()  asm volatile("cp.async.wait_group 1;" ::: "memory")
#define CP_WAIT0()  asm volatile("cp.async.wait_group 0;" ::: "memory")

__device__ __forceinline__ void mma_tf32(float c[4], const uint32_t a[4],
                                         const uint32_t b[2]) {
    asm volatile(
        "mma.sync.aligned.m16n8k8.row.col.f32.tf32.tf32.f32 "
        "{%0,%1,%2,%3}, {%4,%5,%6,%7}, {%8,%9}, {%0,%1,%2,%3};"
        : "+f"(c[0]), "+f"(c[1]), "+f"(c[2]), "+f"(c[3])
        : "r"(a[0]), "r"(a[1]), "r"(a[2]), "r"(a[3]), "r"(b[0]), "r"(b[1]));
}

// ---------------- weight transpose: g_WT[z][n][k] = tf32(W_z[k][n]) ----------
__global__ void __launch_bounds__(256) transpose_kernel(
    const float* __restrict__ Wq, const float* __restrict__ Wk,
    const float* __restrict__ Wv, const float* __restrict__ Wo)
{
    __shared__ float t[32][33];
    const float* src = (blockIdx.z == 0) ? Wq : (blockIdx.z == 1) ? Wk
                     : (blockIdx.z == 2) ? Wv : Wo;
    float* dst = g_WT + (size_t)blockIdx.z * ND * ND;
    int x0 = blockIdx.x * 32, y0 = blockIdx.y * 32;
    int tx = threadIdx.x, ty = threadIdx.y;          // 32 x 8
    #pragma unroll
    for (int j = 0; j < 32; j += 8)
        t[ty + j][tx] = src[(size_t)(y0 + ty + j) * ND + x0 + tx];
    __syncthreads();
    #pragma unroll
    for (int j = 0; j < 32; j += 8)
        dst[(size_t)(x0 + ty + j) * ND + y0 + tx] = tf32f(t[tx][ty + j]);
}

// ---------------- x transpose: g_xT[i][b] = tf32(x[b][i]); also g_xv --------
__global__ void __launch_bounds__(256) xt_kernel(const float* __restrict__ x)
{
    __shared__ uint32_t tile[64][17];
    int tid = threadIdx.x;
    int i0 = blockIdx.x * 64;

    #pragma unroll
    for (int p = 0; p < 4; p++) {
        int b = p * 4 + (tid >> 6);
        int i = tid & 63;
        uint32_t v = f2tf32(x[(size_t)b * LD + i0 + i]);
        tile[i][b] = v;
        g_xv[(size_t)b * LD + i0 + i] = __uint_as_float(v);
    }
    __syncthreads();
    #pragma unroll
    for (int p = 0; p < 4; p++) {
        int i = p * 16 + (tid >> 4);
        int b = tid & 15;
        g_xT[(size_t)(i0 + i) * 16 + b] = __uint_as_float(tile[i][b]);
    }
}

// ---------------- gather: one 64B xT line serves all 16 batches -------------
__global__ void __launch_bounds__(256) gather_kernel(
    const int* __restrict__ pq, const int* __restrict__ pk)
{
    int i = blockIdx.x * 256 + threadIdx.x;          // 0..786431
    const int* pp = blockIdx.y ? pk : pq;
    float* dst    = blockIdx.y ? g_xk : g_xq;
    int idx = pp[i];

    const float4* src = (const float4*)&g_xT[(size_t)idx * 16];
    float4 v0 = src[0], v1 = src[1], v2 = src[2], v3 = src[3];
    float vals[16] = {v0.x, v0.y, v0.z, v0.w, v1.x, v1.y, v1.z, v1.w,
                      v2.x, v2.y, v2.z, v2.w, v3.x, v3.y, v3.z, v3.w};
    #pragma unroll
    for (int b = 0; b < 16; b++)
        dst[(size_t)b * LD + i] = vals[b];
}

// ---------------- tf32 GEMM (cp.async double-buffered, 256 thr, occ 2) ------
#define AS_STRIDE 36
#define TILE_WORDS (128*AS_STRIDE)
#define GEMM_SMEM (4*TILE_WORDS*4)      // 73728 B

__device__ __forceinline__ void gemm_core(
    const float* __restrict__ A,
    const float* __restrict__ BT,
    float*       __restrict__ C,
    const float* __restrict__ bias,
    int mode, float osc)
{
    extern __shared__ uint32_t smg[];
    uint32_t sA = smem_u32(smg);
    uint32_t sB = sA + 2*TILE_WORDS*4;

    int tid  = threadIdx.x;
    int lane = tid & 31, wid = tid >> 5;
    int wm = wid >> 1, wn = wid & 1;          // 4 x 2 warps
    int g = lane >> 2, t = lane & 3;
    int m0 = blockIdx.y * 128, n0 = blockIdx.x * 128;
    int lr = tid >> 3;          // 0..31
    int lc = tid & 7;           // 0..7

    float c[2][8][4];
    #pragma unroll
    for (int mt = 0; mt < 2; mt++)
        #pragma unroll
        for (int nt = 0; nt < 8; nt++)
            #pragma unroll
            for (int i = 0; i < 4; i++) c[mt][nt][i] = 0.f;

    auto issue = [&](int kt, int st) {
        #pragma unroll
        for (int it = 0; it < 4; it++) {
            int r = it * 32 + lr;
            cp16(sA + (st*TILE_WORDS + r*AS_STRIDE + lc*4)*4,
                 &A[(size_t)(m0 + r) * ND + kt*32 + lc*4]);
            cp16(sB + (st*TILE_WORDS + r*AS_STRIDE + lc*4)*4,
                 &BT[(size_t)(n0 + r) * ND + kt*32 + lc*4]);
        }
    };

    issue(0, 0);
    CP_COMMIT();

    for (int kt = 0; kt < 24; kt++) {
        int st = kt & 1;
        if (kt < 23) { issue(kt + 1, st ^ 1); CP_COMMIT(); CP_WAIT1(); }
        else         { CP_WAIT0(); }
        __syncthreads();

        const uint32_t* As = smg + st * TILE_WORDS;
        const uint32_t* Bs = smg + 2*TILE_WORDS + st * TILE_WORDS;
        #pragma unroll
        for (int kk = 0; kk < 4; kk++) {
            int k0 = kk * 8 + t;
            uint32_t a[2][4], b[8][2];
            #pragma unroll
            for (int mt = 0; mt < 2; mt++) {
                int mr = wm * 32 + mt * 16 + g;
                a[mt][0] = As[mr * AS_STRIDE + k0];
                a[mt][1] = As[(mr + 8) * AS_STRIDE + k0];
                a[mt][2] = As[mr * AS_STRIDE + k0 + 4];
                a[mt][3] = As[(mr + 8) * AS_STRIDE + k0 + 4];
            }
            #pragma unroll
            for (int nt = 0; nt < 8; nt++) {
                int nr = wn * 64 + nt * 8 + g;
                b[nt][0] = Bs[nr * AS_STRIDE + k0];
                b[nt][1] = Bs[nr * AS_STRIDE + k0 + 4];
            }
            #pragma unroll
            for (int mt = 0; mt < 2; mt++)
                #pragma unroll
                for (int nt = 0; nt < 8; nt++)
                    mma_tf32(c[mt][nt], a[mt], b[nt]);
        }
        __syncthreads();
    }

    // epilogue
    #pragma unroll
    for (int mt = 0; mt < 2; mt++) {
        int m = m0 + wm * 32 + mt * 16 + g;
        #pragma unroll
        for (int nt = 0; nt < 8; nt++) {
            int n = n0 + wn * 64 + nt * 8 + 2 * t;
            if (mode == 0) {
                int b0i = m >> 10, l = m & 1023;
                int h = n >> 6, dh = n & 63;
                size_t base0 = ((((size_t)b0i * NH + h) * NL + l) << 6) + dh;
                *(float2*)&C[base0] = make_float2(
                    tf32f(c[mt][nt][0]*osc), tf32f(c[mt][nt][1]*osc));
                size_t base2 = ((((size_t)b0i * NH + h) * NL + (l + 8)) << 6) + dh;
                *(float2*)&C[base2] = make_float2(
                    tf32f(c[mt][nt][2]*osc), tf32f(c[mt][nt][3]*osc));
            } else if (mode == 2) {
                int b0i = m >> 10, l = m & 1023;
                int h = n >> 6, dh = n & 63;
                size_t base = (((size_t)b0i * NH + h) * NDH + dh) * NL + l;
                C[base]          = tf32f(c[mt][nt][0]);
                C[base + NL]     = tf32f(c[mt][nt][1]);
                C[base + 8]      = tf32f(c[mt][nt][2]);
                C[base + NL + 8] = tf32f(c[mt][nt][3]);
            } else {
                float2 bb = *(const float2*)&bias[n];
                *(float2*)&C[(size_t)m * ND + n] =
                    make_float2(c[mt][nt][0] + bb.x, c[mt][nt][1] + bb.y);
                *(float2*)&C[(size_t)(m + 8) * ND + n] =
                    make_float2(c[mt][nt][2] + bb.x, c[mt][nt][3] + bb.y);
            }
        }
    }
}

// fused q/k/v projections: blockIdx.z selects which GEMM
__global__ void __launch_bounds__(256, 2) qkv_kernel()
{
    int z = blockIdx.z;
    const float* A  = (z == 0) ? g_xq : (z == 1) ? g_xk : g_xv;
    const float* BT = g_WT + (size_t)z * ND * ND;
    float* C        = (z == 0) ? g_q : (z == 1) ? g_k : g_v;
    float osc       = (z == 0) ? SC_Q : 1.0f;
    gemm_core(A, BT, C, nullptr, (z == 2) ? 2 : 0, osc);
}

// final projection + bias
__global__ void __launch_bounds__(256, 2) proj_kernel(
    const float* __restrict__ bias, float* __restrict__ out)
{
    gemm_core(g_o, g_WT + 3 * (size_t)ND * ND, out, bias, 1, 1.0f);
}

// ---------------- tensor-core flash attention (tf32, single-buffer, occ 3) --
// grid (8 q-tiles of 128, 192 bh), block 128 (4 warps, warp = 32 q-rows).
#define ASTR2 68
#define KV_WORDS (64*ASTR2)                       // 4352 words per buffer
#define ATTN_SMEM ((2*KV_WORDS + 128*ASTR2) * 4)  // 69632 B

__global__ void __launch_bounds__(128, 3) attn_mma_kernel()
{
    extern __shared__ uint32_t smu[];
    uint32_t sb = smem_u32(smu);
    uint32_t (*Ks)[ASTR2] = (uint32_t(*)[ASTR2])smu;
    uint32_t (*Vs)[ASTR2] = (uint32_t(*)[ASTR2])(smu + KV_WORDS);
    uint32_t (*Ps)[ASTR2] = (uint32_t(*)[ASTR2])(smu + 2*KV_WORDS);

    int tid = threadIdx.x, lane = tid & 31, wid = tid >> 5;
    int g = lane >> 2, t = lane & 3;
    int bh = blockIdx.y, qt = blockIdx.x;

    const float* Qg  = g_q + (size_t)bh * NL * NDH + (size_t)qt * 128 * NDH;
    const float* Kg  = g_k + (size_t)bh * NL * NDH;
    const float* VTg = g_v + (size_t)bh * NDH * NL;

    // issue K/V tile kt (single buffer)
    auto issue_kv = [&](int kt) {
        const float* Kt = Kg + (size_t)kt * 64 * 64;
        #pragma unroll
        for (int it = 0; it < 8; it++) {
            int idx = it * 128 + tid;          // 0..1023
            int r = idx >> 4, c4 = (idx & 15) << 2;
            cp16(sb + (r*ASTR2 + c4)*4, &Kt[r * 64 + c4]);
            cp16(sb + (KV_WORDS + r*ASTR2 + c4)*4,
                 &VTg[(size_t)r * NL + kt * 64 + c4]);
        }
    };

    // stage Q (128 x 64, tf32 bits) into Ps, pull fragments
    #pragma unroll
    for (int it = 0; it < 16; it++) {
        int idx = it * 128 + tid;
        int r = idx >> 4, c4 = (idx & 15) << 2;
        *(uint4*)&Ps[r][c4] = *(const uint4*)&Qg[r * 64 + c4];
    }
    __syncthreads();

    uint32_t aq[2][8][4];
    #pragma unroll
    for (int h = 0; h < 2; h++) {
        int mr = wid * 32 + h * 16 + g;
        #pragma unroll
        for (int kk = 0; kk < 8; kk++) {
            aq[h][kk][0] = Ps[mr][kk*8 + t];
            aq[h][kk][1] = Ps[mr + 8][kk*8 + t];
            aq[h][kk][2] = Ps[mr][kk*8 + t + 4];
            aq[h][kk][3] = Ps[mr + 8][kk*8 + t + 4];
        }
    }

    float mI[2][2], lI[2][2];
    #pragma unroll
    for (int h = 0; h < 2; h++) { mI[h][0] = mI[h][1] = -1e30f; lI[h][0] = lI[h][1] = 0.f; }
    float o[2][8][4];
    #pragma unroll
    for (int h = 0; h < 2; h++)
        #pragma unroll
        for (int nt = 0; nt < 8; nt++)
            #pragma unroll
            for (int i = 0; i < 4; i++) o[h][nt][i] = 0.f;

    for (int kt = 0; kt < 16; kt++) {
        if (kt) __syncthreads();   // all warps done reading Ks/Vs of kt-1
        issue_kv(kt);
        CP_COMMIT();
        CP_WAIT0();
        __syncthreads();

        #pragma unroll
        for (int h = 0; h < 2; h++) {
            int mr = wid * 32 + h * 16 + g;
            float s[8][4];
            #pragma unroll
            for (int nt = 0; nt < 8; nt++)
                #pragma unroll
                for (int i = 0; i < 4; i++) s[nt][i] = 0.f;
            #pragma unroll
            for (int kk = 0; kk < 8; kk++) {
                #pragma unroll
                for (int nt = 0; nt < 8; nt++) {
                    uint32_t b[2];
                    int nr = nt * 8 + g;
                    b[0] = Ks[nr][kk*8 + t];
                    b[1] = Ks[nr][kk*8 + t + 4];
                    mma_tf32(s[nt], aq[h][kk], b);
                }
            }
            float mx0 = -1e30f, mx1 = -1e30f;
            #pragma unroll
            for (int nt = 0; nt < 8; nt++) {
                mx0 = fmaxf(mx0, fmaxf(s[nt][0], s[nt][1]));
                mx1 = fmaxf(mx1, fmaxf(s[nt][2], s[nt][3]));
            }
            mx0 = fmaxf(mx0, __shfl_xor_sync(0xffffffffu, mx0, 1));
            mx0 = fmaxf(mx0, __shfl_xor_sync(0xffffffffu, mx0, 2));
            mx1 = fmaxf(mx1, __shfl_xor_sync(0xffffffffu, mx1, 1));
            mx1 = fmaxf(mx1, __shfl_xor_sync(0xffffffffu, mx1, 2));

            float mn0 = fmaxf(mI[h][0], mx0), mn1 = fmaxf(mI[h][1], mx1);
            float corr0 = ex2(mI[h][0] - mn0), corr1 = ex2(mI[h][1] - mn1);
            mI[h][0] = mn0; mI[h][1] = mn1;

            float sum0 = 0.f, sum1 = 0.f;
            #pragma unroll
            for (int nt = 0; nt < 8; nt++) {
                float p0 = ex2(s[nt][0] - mn0);
                float p1 = ex2(s[nt][1] - mn0);
                float p2 = ex2(s[nt][2] - mn1);
                float p3 = ex2(s[nt][3] - mn1);
                sum0 += p0 + p1; sum1 += p2 + p3;
                int col = nt * 8 + 2 * t;
                *(uint2*)&Ps[mr][col]     = make_uint2(f2tf32(p0), f2tf32(p1));
                *(uint2*)&Ps[mr + 8][col] = make_uint2(f2tf32(p2), f2tf32(p3));
            }
            sum0 += __shfl_xor_sync(0xffffffffu, sum0, 1);
            sum0 += __shfl_xor_sync(0xffffffffu, sum0, 2);
            sum1 += __shfl_xor_sync(0xffffffffu, sum1, 1);
            sum1 += __shfl_xor_sync(0xffffffffu, sum1, 2);
            lI[h][0] = lI[h][0] * corr0 + sum0;
            lI[h][1] = lI[h][1] * corr1 + sum1;

            #pragma unroll
            for (int nt = 0; nt < 8; nt++) {
                o[h][nt][0] *= corr0; o[h][nt][1] *= corr0;
                o[h][nt][2] *= corr1; o[h][nt][3] *= corr1;
            }
        }
        __syncwarp();

        // O += P @ V : V b-fragments shared across both halves; Ps warp-private
        #pragma unroll
        for (int kk = 0; kk < 8; kk++) {
            uint32_t vb[8][2];
            #pragma unroll
            for (int nt = 0; nt < 8; nt++) {
                int nr = nt * 8 + g;
                vb[nt][0] = Vs[nr][kk*8 + t];
                vb[nt][1] = Vs[nr][kk*8 + t + 4];
            }
            #pragma unroll
            for (int h = 0; h < 2; h++) {
                int mr = wid * 32 + h * 16 + g;
                uint32_t ap[4];
                ap[0] = Ps[mr][kk*8 + t];
                ap[1] = Ps[mr + 8][kk*8 + t];
                ap[2] = Ps[mr][kk*8 + t + 4];
                ap[3] = Ps[mr + 8][kk*8 + t + 4];
                #pragma unroll
                for (int nt = 0; nt < 8; nt++)
                    mma_tf32(o[h][nt], ap, vb[nt]);
            }
        }
    }

    int bb = bh / NH, hh = bh % NH;
    float* Og = g_o + ((size_t)bb * NL + qt * 128) * ND + hh * 64;
    #pragma unroll
    for (int h = 0; h < 2; h++) {
        float inv0 = 1.f / lI[h][0], inv1 = 1.f / lI[h][1];
        int mr = wid * 32 + h * 16 + g;
        #pragma unroll
        for (int nt = 0; nt < 8; nt++) {
            int col = nt * 8 + 2 * t;
            *(float2*)&Og[(size_t)mr * ND + col] = make_float2(
                tf32f(o[h][nt][0] * inv0), tf32f(o[h][nt][1] * inv0));
            *(float2*)&Og[(size_t)(mr + 8) * ND + col] = make_float2(
                tf32f(o[h][nt][2] * inv1), tf32f(o[h][nt][3] * inv1));
        }
    }
}

// ---------------- launch -----------------------------------------------------
extern "C" void kernel_launch(void* const* d_in, const int* in_sizes, int n_in,
                              void* d_out, int out_size)
{
    const float* x  = (const float*)d_in[0];
    const float* Wq = (const float*)d_in[1];
    const float* Wk = (const float*)d_in[2];
    const float* Wv = (const float*)d_in[3];
    const float* Wo = (const float*)d_in[4];
    const float* bo = (const float*)d_in[5];
    const int*   pq = (const int*)d_in[6];
    const int*   pk = (const int*)d_in[7];
    float* out = (float*)d_out;

    cudaFuncSetAttribute(attn_mma_kernel,
                         cudaFuncAttributeMaxDynamicSharedMemorySize, ATTN_SMEM);
    cudaFuncSetAttribute(qkv_kernel,
                         cudaFuncAttributeMaxDynamicSharedMemorySize, GEMM_SMEM);
    cudaFuncSetAttribute(proj_kernel,
                         cudaFuncAttributeMaxDynamicSharedMemorySize, GEMM_SMEM);

    // 0. weight transposes (tf32 bits) + x transpose (xT + xv)
    transpose_kernel<<<dim3(24, 24, 4), dim3(32, 8)>>>(Wq, Wk, Wv, Wo);
    xt_kernel<<<LD / 64, 256>>>(x);

    // 1. gathers: 64B xT line per index serves all 16 batches
    gather_kernel<<<dim3(LD / 256, 2), 256>>>(pq, pk);

    // 2. fused q/k/v projections (cp.async pipelined tf32 mma, occ 2)
    qkv_kernel<<<dim3(ND / 128, NM / 128, 3), 256, GEMM_SMEM>>>();

    // 3. attention (tensor-core flash, single-buffered K/V, occ 3)
    attn_mma_kernel<<<dim3(NL / 128, NB * NH), 128, ATTN_SMEM>>>();

    // 4. output projection + bias
    proj_kernel<<<dim3(ND / 128, NM / 128), 256, GEMM_SMEM>>>(bo, out);
}